// round 6
// baseline (speedup 1.0000x reference)
#include <cuda_runtime.h>
#include <cstddef>

#define NA 100000
#define NB 100000
#define ND 50000
#define H  128
#define OUTD 16
#define NE 600000

// ---------------- scratch (static device globals; no allocation) ----------------
// g_agg0 doubles as layer-1 "t" buffer (stream-ordered reuse, no hazard).
__device__ float g_agg0[ND * 256];          // L0: [aggA | aggB]; later L1: [t2 | t3]
__device__ float g_h0d [ND * H];            // layer0 output (d)
__device__ float g_h1a [NA * H];            // layer1 pre-activation sums
__device__ float g_h1b [NB * H];
__device__ float g_u0  [NA * OUTD];
__device__ float g_u1  [NB * OUTD];
__device__ float g_aggd[ND * 2 * OUTD];
__device__ float g_deg0[ND];
__device__ float g_deg1[ND];
__device__ float g_deg2[NA];
__device__ float g_deg3[NB];
__device__ float g_w0[256 * 128];           // [W00 ; W01]  (K=256, N=128)
__device__ float g_w1[128 * 256];           // cols 0-127 = W12, 128-255 = W13
__device__ float g_w2[2 * 128 * OUTD];      // W20 then W21

// ---------------- helpers ----------------
__device__ __forceinline__ void red4(float* p, float4 v) {
    asm volatile("red.global.add.v4.f32 [%0], {%1, %2, %3, %4};"
                 :: "l"(p), "f"(v.x), "f"(v.y), "f"(v.z), "f"(v.w) : "memory");
}
__device__ __forceinline__ void red1(float* p, float v) {
    asm volatile("red.global.add.f32 [%0], %1;" :: "l"(p), "f"(v) : "memory");
}

// W_r = coef[r,0]*basis[0] + coef[r,1]*basis[1], written with output leading dim
__global__ void make_w(const float* __restrict__ basis, const float* __restrict__ coef,
                       int r, int din, int dout, int out_ld, float* __restrict__ out)
{
    float c0 = coef[r * 2 + 0], c1 = coef[r * 2 + 1];
    int n = din * dout;
    for (int i = blockIdx.x * blockDim.x + threadIdx.x; i < n; i += gridDim.x * blockDim.x) {
        float v = c0 * basis[i] + c1 * basis[n + i];
        out[(i / dout) * out_ld + (i % dout)] = v;
    }
}

// one warp per 4 edges: 4 independent LDG.128 in flight before the REDs issue.
template<bool COUNT>
__global__ void scatter128(const float* __restrict__ src, int sld, int soff,
                           const int* __restrict__ es, const int* __restrict__ ed,
                           float* __restrict__ dst, int dld, int doff,
                           float* __restrict__ deg)
{
    int lane = threadIdx.x & 31;
    int w    = (blockIdx.x * blockDim.x + threadIdx.x) >> 5;
    int nw   = (gridDim.x * blockDim.x) >> 5;
    int e = w * 4;
    for (; e + 3 < NE; e += nw * 4) {
        int s0 = es[e],     t0 = ed[e];
        int s1 = es[e + 1], t1 = ed[e + 1];
        int s2 = es[e + 2], t2 = ed[e + 2];
        int s3 = es[e + 3], t3 = ed[e + 3];
        float4 v0 = __ldg((const float4*)(src + (size_t)s0 * sld + soff) + lane);
        float4 v1 = __ldg((const float4*)(src + (size_t)s1 * sld + soff) + lane);
        float4 v2 = __ldg((const float4*)(src + (size_t)s2 * sld + soff) + lane);
        float4 v3 = __ldg((const float4*)(src + (size_t)s3 * sld + soff) + lane);
        red4(dst + (size_t)t0 * dld + doff + lane * 4, v0);
        red4(dst + (size_t)t1 * dld + doff + lane * 4, v1);
        red4(dst + (size_t)t2 * dld + doff + lane * 4, v2);
        red4(dst + (size_t)t3 * dld + doff + lane * 4, v3);
        if (COUNT && lane < 4) {
            // t0..t3 are warp-uniform (loaded from uniform addresses); direct select
            int tsel = (lane == 0) ? t0 : (lane == 1) ? t1 : (lane == 2) ? t2 : t3;
            red1(deg + tsel, 1.0f);
        }
    }
    // tail (NE % 4 == 0 here, but keep general)
    for (; e < NE; e++) {
        int s = es[e], t = ed[e];
        float4 v = __ldg((const float4*)(src + (size_t)s * sld + soff) + lane);
        red4(dst + (size_t)t * dld + doff + lane * 4, v);
        if (COUNT && lane == 0) red1(deg + t, 1.0f);
    }
}

// 4 threads per edge, consecutive-pair unroll: 16 f32 rows, 2-deep MLP
__global__ void scatter16(const float* __restrict__ u,
                          const int* __restrict__ es, const int* __restrict__ ed,
                          float* __restrict__ dst)
{
    int q      = blockIdx.x * blockDim.x + threadIdx.x;
    int sub    = q & 3;
    int e      = (q >> 2) * 2;
    int stride = (gridDim.x * blockDim.x) >> 1;   // quads * 2 edges
    for (; e + 1 < NE; e += stride) {
        int s0 = es[e],     t0 = ed[e];
        int s1 = es[e + 1], t1 = ed[e + 1];
        float4 v0 = __ldg((const float4*)(u + (size_t)s0 * OUTD) + sub);
        float4 v1 = __ldg((const float4*)(u + (size_t)s1 * OUTD) + sub);
        red4(dst + (size_t)t0 * OUTD + sub * 4, v0);
        red4(dst + (size_t)t1 * OUTD + sub * 4, v1);
    }
    if (e < NE) {
        int s = es[e], t = ed[e];
        float4 v = __ldg((const float4*)(u + (size_t)s * OUTD) + sub);
        red4(dst + (size_t)t * OUTD + sub * 4, v);
    }
}

// double-buffered tiled SGEMM: BM=128, BN=128, BK=8, 256 threads, 8x8 per thread,
// one __syncthreads per k-step.
// SCALED: A rows scaled by 1/max(deg,1), deg0 for k<128, deg1 for k>=128 (layer-0 fusion)
// RELU_BIAS: epilogue out = relu(out + bias[col])
template<bool SCALED, bool RELU_BIAS>
__global__ void __launch_bounds__(256)
sgemm(const float* __restrict__ A, int lda,
      const float* __restrict__ B,
      float* __restrict__ C,
      int M, int N, int K,
      const float* __restrict__ dg0, const float* __restrict__ dg1,
      const float* __restrict__ bias)
{
    __shared__ float As[2][8][128];
    __shared__ float Bs[2][8][128];
    const int tid = threadIdx.x;
    const int tx  = tid & 15;
    const int ty  = tid >> 4;
    const int m0  = blockIdx.x * 128;
    const int n0  = blockIdx.y * 128;

    const int arow = tid >> 1;
    const int acol = (tid & 1) << 2;
    const int brow = tid >> 5;
    const int bcol = (tid & 31) << 2;

    const int  gm_a = m0 + arow;
    const bool aok  = gm_a < M;
    float s0 = 1.f, s1 = 1.f;
    if (SCALED && aok) {
        s0 = 1.f / fmaxf(__ldg(dg0 + gm_a), 1.f);
        s1 = 1.f / fmaxf(__ldg(dg1 + gm_a), 1.f);
    }
    const float* Ap = A + (size_t)gm_a * lda + acol;
    const float* Bp = B + (size_t)brow * N + n0 + bcol;

    float acc[8][8];
    #pragma unroll
    for (int i = 0; i < 8; i++)
        #pragma unroll
        for (int j = 0; j < 8; j++) acc[i][j] = 0.f;

    // ---- prologue: load k0=0 tile into buffer 0
    {
        float4 a4 = make_float4(0.f, 0.f, 0.f, 0.f);
        if (aok) a4 = *(const float4*)(Ap);
        if (SCALED) { a4.x *= s0; a4.y *= s0; a4.z *= s0; a4.w *= s0; }
        float4 b4 = *(const float4*)(Bp);
        As[0][acol + 0][arow] = a4.x;
        As[0][acol + 1][arow] = a4.y;
        As[0][acol + 2][arow] = a4.z;
        As[0][acol + 3][arow] = a4.w;
        *(float4*)&Bs[0][brow][bcol] = b4;
    }
    __syncthreads();

    for (int k0 = 0; k0 < K; k0 += 8) {
        const int cur  = (k0 >> 3) & 1;
        const bool more = (k0 + 8) < K;

        // prefetch next tile while computing current
        float4 a4n, b4n;
        if (more) {
            a4n = make_float4(0.f, 0.f, 0.f, 0.f);
            if (aok) a4n = *(const float4*)(Ap + k0 + 8);
            if (SCALED) {
                float s = ((k0 + 8) >= H) ? s1 : s0;
                a4n.x *= s; a4n.y *= s; a4n.z *= s; a4n.w *= s;
            }
            b4n = *(const float4*)(Bp + (size_t)(k0 + 8) * N);
        }

        #pragma unroll
        for (int kk = 0; kk < 8; kk++) {
            float ar[8], br[8];
            *(float4*)(ar)     = *(const float4*)&As[cur][kk][ty * 8];
            *(float4*)(ar + 4) = *(const float4*)&As[cur][kk][ty * 8 + 4];
            *(float4*)(br)     = *(const float4*)&Bs[cur][kk][tx * 4];
            *(float4*)(br + 4) = *(const float4*)&Bs[cur][kk][64 + tx * 4];
            #pragma unroll
            for (int i = 0; i < 8; i++)
                #pragma unroll
                for (int j = 0; j < 8; j++)
                    acc[i][j] += ar[i] * br[j];
        }

        if (more) {
            const int nxt = cur ^ 1;
            As[nxt][acol + 0][arow] = a4n.x;
            As[nxt][acol + 1][arow] = a4n.y;
            As[nxt][acol + 2][arow] = a4n.z;
            As[nxt][acol + 3][arow] = a4n.w;
            *(float4*)&Bs[nxt][brow][bcol] = b4n;
            __syncthreads();
        }
    }

    #pragma unroll
    for (int i = 0; i < 8; i++) {
        int gm = m0 + ty * 8 + i;
        if (gm >= M) continue;
        #pragma unroll
        for (int half = 0; half < 2; half++) {
            int nc = n0 + half * 64 + tx * 4;
            float4 v;
            v.x = acc[i][half * 4 + 0];
            v.y = acc[i][half * 4 + 1];
            v.z = acc[i][half * 4 + 2];
            v.w = acc[i][half * 4 + 3];
            if (RELU_BIAS) {
                v.x = fmaxf(v.x + __ldg(bias + nc + 0), 0.f);
                v.y = fmaxf(v.y + __ldg(bias + nc + 1), 0.f);
                v.z = fmaxf(v.z + __ldg(bias + nc + 2), 0.f);
                v.w = fmaxf(v.w + __ldg(bias + nc + 3), 0.f);
            }
            *(float4*)(C + (size_t)gm * N + nc) = v;
        }
    }
}

// narrow GEMM with fused layer-1 epilogue:
// U = relu(A/max(deg,1) + bias) @ W,  [M,128] x [128,16]
__global__ void __launch_bounds__(256)
gemm_n16(const float* __restrict__ A, const float* __restrict__ W,
         const float* __restrict__ deg, const float* __restrict__ bias,
         float* __restrict__ U, int M)
{
    __shared__ float Ws[128 * OUTD];
    __shared__ float As[64][132];
    int tid = threadIdx.x;
    int r0  = blockIdx.x * 64;

    for (int i = tid; i < 128 * OUTD; i += 256) Ws[i] = W[i];
    for (int f = tid; f < 2048; f += 256) {          // 64 rows x 32 float4
        int row = f >> 5, k4 = (f & 31) << 2;
        int gr = r0 + row;
        float4 v = make_float4(0.f, 0.f, 0.f, 0.f);
        if (gr < M) {
            float inv = 1.f / fmaxf(__ldg(deg + gr), 1.f);
            v = *(const float4*)(A + (size_t)gr * H + k4);
            v.x = fmaxf(v.x * inv + __ldg(bias + k4 + 0), 0.f);
            v.y = fmaxf(v.y * inv + __ldg(bias + k4 + 1), 0.f);
            v.z = fmaxf(v.z * inv + __ldg(bias + k4 + 2), 0.f);
            v.w = fmaxf(v.w * inv + __ldg(bias + k4 + 3), 0.f);
        }
        *(float4*)&As[row][k4] = v;
    }
    __syncthreads();

    int col = tid & 15;
    int rb  = (tid >> 4) * 4;
    float a0 = 0.f, a1 = 0.f, a2 = 0.f, a3 = 0.f;
    #pragma unroll 8
    for (int k = 0; k < 128; k++) {
        float w = Ws[k * OUTD + col];
        a0 += As[rb + 0][k] * w;
        a1 += As[rb + 1][k] * w;
        a2 += As[rb + 2][k] * w;
        a3 += As[rb + 3][k] * w;
    }
    if (r0 + rb + 0 < M) U[(size_t)(r0 + rb + 0) * OUTD + col] = a0;
    if (r0 + rb + 1 < M) U[(size_t)(r0 + rb + 1) * OUTD + col] = a1;
    if (r0 + rb + 2 < M) U[(size_t)(r0 + rb + 2) * OUTD + col] = a2;
    if (r0 + rb + 3 < M) U[(size_t)(r0 + rb + 3) * OUTD + col] = a3;
}

__global__ void final_combine(const float* __restrict__ aggd,
                              const float* __restrict__ deg0, const float* __restrict__ deg1,
                              const float* __restrict__ bias2, float* __restrict__ out)
{
    int i = blockIdx.x * blockDim.x + threadIdx.x;
    if (i >= ND * OUTD) return;
    int m = i >> 4, c = i & 15;
    float i0 = 1.f / fmaxf(__ldg(deg0 + m), 1.f);
    float i1 = 1.f / fmaxf(__ldg(deg1 + m), 1.f);
    out[i] = aggd[i] * i0 + aggd[ND * OUTD + i] * i1 + __ldg(bias2 + c);
}

// ---------------- launch ----------------
extern "C" void kernel_launch(void* const* d_in, const int* in_sizes, int n_in,
                              void* d_out, int out_size)
{
    const float* feat_a = (const float*)d_in[0];
    const float* feat_b = (const float*)d_in[1];
    const float* basis0 = (const float*)d_in[3];
    const float* coef0  = (const float*)d_in[4];
    const float* bias0  = (const float*)d_in[5];
    const float* basis1 = (const float*)d_in[6];
    const float* coef1  = (const float*)d_in[7];
    const float* bias1  = (const float*)d_in[8];
    const float* basis2 = (const float*)d_in[9];
    const float* coef2  = (const float*)d_in[10];
    const float* bias2  = (const float*)d_in[11];
    const int* e0s = (const int*)d_in[12]; const int* e0d = (const int*)d_in[13];
    const int* e1s = (const int*)d_in[14]; const int* e1d = (const int*)d_in[15];
    const int* e2s = (const int*)d_in[16]; const int* e2d = (const int*)d_in[17];
    const int* e3s = (const int*)d_in[18]; const int* e3d = (const int*)d_in[19];
    float* out = (float*)d_out;

    void *p;
    float *agg0, *h0d, *t, *h1a, *h1b, *u0, *u1, *aggd, *dg0, *dg1, *dg2, *dg3, *w0, *w1, *w2;
    cudaGetSymbolAddress(&p, g_agg0); agg0 = (float*)p; t = agg0;  // aliased reuse
    cudaGetSymbolAddress(&p, g_h0d);  h0d  = (float*)p;
    cudaGetSymbolAddress(&p, g_h1a);  h1a  = (float*)p;
    cudaGetSymbolAddress(&p, g_h1b);  h1b  = (float*)p;
    cudaGetSymbolAddress(&p, g_u0);   u0   = (float*)p;
    cudaGetSymbolAddress(&p, g_u1);   u1   = (float*)p;
    cudaGetSymbolAddress(&p, g_aggd); aggd = (float*)p;
    cudaGetSymbolAddress(&p, g_deg0); dg0  = (float*)p;
    cudaGetSymbolAddress(&p, g_deg1); dg1  = (float*)p;
    cudaGetSymbolAddress(&p, g_deg2); dg2  = (float*)p;
    cudaGetSymbolAddress(&p, g_deg3); dg3  = (float*)p;
    cudaGetSymbolAddress(&p, g_w0);   w0   = (float*)p;
    cudaGetSymbolAddress(&p, g_w1);   w1   = (float*)p;
    cudaGetSymbolAddress(&p, g_w2);   w2   = (float*)p;

    cudaMemsetAsync(agg0, 0, sizeof(float) * (size_t)ND * 256);
    cudaMemsetAsync(h1a,  0, sizeof(float) * (size_t)NA * H);
    cudaMemsetAsync(h1b,  0, sizeof(float) * (size_t)NB * H);
    cudaMemsetAsync(aggd, 0, sizeof(float) * (size_t)ND * 2 * OUTD);
    cudaMemsetAsync(dg0,  0, sizeof(float) * ND);
    cudaMemsetAsync(dg1,  0, sizeof(float) * ND);
    cudaMemsetAsync(dg2,  0, sizeof(float) * NA);
    cudaMemsetAsync(dg3,  0, sizeof(float) * NB);

    // relation weights (only the 6 matrices the pruned dataflow needs)
    make_w<<<32, 256>>>(basis0, coef0, 0, H, H, H,   w0);                // W00 -> rows 0-127
    make_w<<<32, 256>>>(basis0, coef0, 1, H, H, H,   w0 + H * H);        // W01 -> rows 128-255
    make_w<<<32, 256>>>(basis1, coef1, 2, H, H, 256, w1);                // W12 -> cols 0-127
    make_w<<<32, 256>>>(basis1, coef1, 3, H, H, 256, w1 + 128);          // W13 -> cols 128-255
    make_w<<<32, 256>>>(basis2, coef2, 0, H, OUTD, OUTD, w2);            // W20
    make_w<<<32, 256>>>(basis2, coef2, 1, H, OUTD, OUTD, w2 + H * OUTD); // W21

    // ---- layer 0: aggregate feat_a/feat_b into d, then fused K=256 GEMM + bias + relu
    scatter128<true><<<4096, 256>>>(feat_a, H, 0, e0s, e0d, agg0, 256, 0,   dg0);
    scatter128<true><<<4096, 256>>>(feat_b, H, 0, e1s, e1d, agg0, 256, 128, dg1);
    dim3 g0((ND + 127) / 128, 1);
    sgemm<true, true><<<g0, 256>>>(agg0, 256, w0, h0d, ND, H, 256, dg0, dg1, bias0);

    // ---- layer 1: transform first (50k rows), then scatter 128-dim to a and b
    dim3 g1((ND + 127) / 128, 2);
    sgemm<false, false><<<g1, 256>>>(h0d, H, w1, t, ND, 256, H, nullptr, nullptr, nullptr);
    scatter128<true><<<4096, 256>>>(t, 256, 0,   e2s, e2d, h1a, H, 0, dg2);
    scatter128<true><<<4096, 256>>>(t, 256, 128, e3s, e3d, h1b, H, 0, dg3);

    // ---- layer 2: fused (deg-norm + bias + relu) into narrow GEMM, then 16-dim scatter
    gemm_n16<<<(NA + 63) / 64, 256>>>(h1a, w2,            dg2, bias1, u0, NA);
    gemm_n16<<<(NB + 63) / 64, 256>>>(h1b, w2 + H * OUTD, dg3, bias1, u1, NB);
    scatter16<<<2048, 256>>>(u0, e0s, e0d, aggd);
    scatter16<<<2048, 256>>>(u1, e1s, e1d, aggd + ND * OUTD);
    final_combine<<<(ND * OUTD + 255) / 256, 256>>>(aggd, dg0, dg1, bias2, out);
}

// round 15
// speedup vs baseline: 1.0470x; 1.0470x over previous
#include <cuda_runtime.h>
#include <cstddef>
#include <cstdint>

#define NA 100000
#define NB 100000
#define ND 50000
#define H  128
#define OUTD 16
#define NE 600000

// ---------------- scratch (static device globals; no allocation) ----------------
__device__ float g_agg0[ND * 256];          // L0: [aggA | aggB]; later L1: [t2 | t3]
__device__ float g_h0d [ND * H];
__device__ float g_h1a [NA * H];
__device__ float g_h1b [NB * H];
__device__ float g_u0  [NA * OUTD];
__device__ float g_u1  [NB * OUTD];
__device__ float g_aggd[ND * 2 * OUTD];
__device__ float g_deg0[ND];
__device__ float g_deg1[ND];
__device__ float g_deg2[NA];
__device__ float g_deg3[NB];
__device__ float g_w0[256 * 128];           // [W00 ; W01]  (K=256, N=128)
__device__ float g_w1[128 * 256];           // cols 0-127 = W12, 128-255 = W13
__device__ float g_w2[2 * 128 * OUTD];      // W20 then W21

// ---------------- helpers ----------------
__device__ __forceinline__ void red4(float* p, float4 v) {
    asm volatile("red.global.add.v4.f32 [%0], {%1, %2, %3, %4};"
                 :: "l"(p), "f"(v.x), "f"(v.y), "f"(v.z), "f"(v.w) : "memory");
}
__device__ __forceinline__ void red1(float* p, float v) {
    asm volatile("red.global.add.f32 [%0], %1;" :: "l"(p), "f"(v) : "memory");
}
__device__ __forceinline__ uint32_t f2tf32(float f) {
    uint32_t u;
    asm("cvt.rna.tf32.f32 %0, %1;" : "=r"(u) : "f"(f));
    return u;
}
__device__ __forceinline__ void mma_tf32(float* d, const uint32_t* a, const uint32_t* b) {
    asm volatile(
        "mma.sync.aligned.m16n8k8.row.col.f32.tf32.tf32.f32 "
        "{%0,%1,%2,%3}, {%4,%5,%6,%7}, {%8,%9}, {%0,%1,%2,%3};\n"
        : "+f"(d[0]), "+f"(d[1]), "+f"(d[2]), "+f"(d[3])
        : "r"(a[0]), "r"(a[1]), "r"(a[2]), "r"(a[3]), "r"(b[0]), "r"(b[1]));
}

// W_r = coef[r,0]*basis[0] + coef[r,1]*basis[1]
__global__ void make_w(const float* __restrict__ basis, const float* __restrict__ coef,
                       int r, int din, int dout, int out_ld, float* __restrict__ out)
{
    float c0 = coef[r * 2 + 0], c1 = coef[r * 2 + 1];
    int n = din * dout;
    for (int i = blockIdx.x * blockDim.x + threadIdx.x; i < n; i += gridDim.x * blockDim.x) {
        float v = c0 * basis[i] + c1 * basis[n + i];
        out[(i / dout) * out_ld + (i % dout)] = v;
    }
}

// one warp per 4 edges: 4 independent LDG.128 in flight before the REDs issue.
template<bool COUNT>
__global__ void scatter128(const float* __restrict__ src, int sld, int soff,
                           const int* __restrict__ es, const int* __restrict__ ed,
                           float* __restrict__ dst, int dld, int doff,
                           float* __restrict__ deg)
{
    int lane = threadIdx.x & 31;
    int w    = (blockIdx.x * blockDim.x + threadIdx.x) >> 5;
    int nw   = (gridDim.x * blockDim.x) >> 5;
    int e = w * 4;
    for (; e + 3 < NE; e += nw * 4) {
        int s0 = es[e],     t0 = ed[e];
        int s1 = es[e + 1], t1 = ed[e + 1];
        int s2 = es[e + 2], t2 = ed[e + 2];
        int s3 = es[e + 3], t3 = ed[e + 3];
        float4 v0 = __ldg((const float4*)(src + (size_t)s0 * sld + soff) + lane);
        float4 v1 = __ldg((const float4*)(src + (size_t)s1 * sld + soff) + lane);
        float4 v2 = __ldg((const float4*)(src + (size_t)s2 * sld + soff) + lane);
        float4 v3 = __ldg((const float4*)(src + (size_t)s3 * sld + soff) + lane);
        red4(dst + (size_t)t0 * dld + doff + lane * 4, v0);
        red4(dst + (size_t)t1 * dld + doff + lane * 4, v1);
        red4(dst + (size_t)t2 * dld + doff + lane * 4, v2);
        red4(dst + (size_t)t3 * dld + doff + lane * 4, v3);
        if (COUNT && lane < 4) {
            int tsel = (lane == 0) ? t0 : (lane == 1) ? t1 : (lane == 2) ? t2 : t3;
            red1(deg + tsel, 1.0f);
        }
    }
    for (; e < NE; e++) {
        int s = es[e], t = ed[e];
        float4 v = __ldg((const float4*)(src + (size_t)s * sld + soff) + lane);
        red4(dst + (size_t)t * dld + doff + lane * 4, v);
        if (COUNT && lane == 0) red1(deg + t, 1.0f);
    }
}

// 4 threads per edge, consecutive-pair unroll: 16 f32 rows, 2-deep MLP
__global__ void scatter16(const float* __restrict__ u,
                          const int* __restrict__ es, const int* __restrict__ ed,
                          float* __restrict__ dst)
{
    int q      = blockIdx.x * blockDim.x + threadIdx.x;
    int sub    = q & 3;
    int e      = (q >> 2) * 2;
    int stride = (gridDim.x * blockDim.x) >> 1;
    for (; e + 1 < NE; e += stride) {
        int s0 = es[e],     t0 = ed[e];
        int s1 = es[e + 1], t1 = ed[e + 1];
        float4 v0 = __ldg((const float4*)(u + (size_t)s0 * OUTD) + sub);
        float4 v1 = __ldg((const float4*)(u + (size_t)s1 * OUTD) + sub);
        red4(dst + (size_t)t0 * OUTD + sub * 4, v0);
        red4(dst + (size_t)t1 * OUTD + sub * 4, v1);
    }
    if (e < NE) {
        int s = es[e], t = ed[e];
        float4 v = __ldg((const float4*)(u + (size_t)s * OUTD) + sub);
        red4(dst + (size_t)t * OUTD + sub * 4, v);
    }
}

// ---------------- TF32x3 tensor-core GEMM ----------------
// C[M,128] (per CTA col-block) = A[M,K] x B[K,N], BM=128 BN=128 BK=16,
// 256 threads = 8 warps (4 M x 2 N), warp tile 32x64 of m16n8k8 mma.
// fp32-accurate via 3-term tf32 split: ah*bh + ah*bl + al*bh.
// SCALED: A row r scaled by 1/max(deg,1): dg0 for k<128, dg1 for k>=128.
// RELU_BIAS: C = relu(C + bias[col]).
template<bool SCALED, bool RELU_BIAS>
__global__ void __launch_bounds__(256)
tgemm(const float* __restrict__ A, int lda,
      const float* __restrict__ B, int ldb,
      float* __restrict__ C, int ldc,
      int M, int K,
      const float* __restrict__ dg0, const float* __restrict__ dg1,
      const float* __restrict__ bias)
{
    // A smem: row stride 20 (frag loads conflict-free: bank sep 4 > lc-delta 3)
    // B smem: row stride 136 (frag-load banks = lc*8+lr, a 0..31 permutation)
    __shared__ uint32_t Ah[128][20], Al[128][20];
    __shared__ uint32_t Bh[16][136], Bl[16][136];

    const int tid  = threadIdx.x;
    const int lane = tid & 31;
    const int wid  = tid >> 5;
    const int wm   = wid & 3;          // M warp row (32 each)
    const int wn   = wid >> 2;         // N warp col (64 each)
    const int m0   = blockIdx.x * 128;
    const int n0   = blockIdx.y * 128;
    const int lr   = lane >> 2;        // 0..7
    const int lc   = lane & 3;         // 0..3

    // A loader role: one row per thread pair
    const int arow = tid >> 1;
    const int kq   = (tid & 1) * 8;
    const int gm   = m0 + arow;
    const bool aok = gm < M;
    float s0 = 1.f, s1 = 1.f;
    if (SCALED && aok) {
        s0 = 1.f / fmaxf(__ldg(dg0 + gm), 1.f);
        s1 = 1.f / fmaxf(__ldg(dg1 + gm), 1.f);
    }
    const float* Ap = A + (size_t)gm * lda + kq;
    // B loader role
    const int brow = tid >> 4;
    const int bcol = (tid & 15) * 8;
    const float* Bp = B + (size_t)brow * ldb + n0 + bcol;

    float acc[2][8][4];
    #pragma unroll
    for (int mt = 0; mt < 2; mt++)
        #pragma unroll
        for (int nt = 0; nt < 8; nt++)
            #pragma unroll
            for (int i = 0; i < 4; i++) acc[mt][nt][i] = 0.f;

    for (int k0 = 0; k0 < K; k0 += 16) {
        // global loads
        float af[8] = {0.f, 0.f, 0.f, 0.f, 0.f, 0.f, 0.f, 0.f};
        if (aok) {
            *(float4*)(af)     = *(const float4*)(Ap + k0);
            *(float4*)(af + 4) = *(const float4*)(Ap + k0 + 4);
            if (SCALED) {
                float s = (k0 >= H) ? s1 : s0;
                #pragma unroll
                for (int j = 0; j < 8; j++) af[j] *= s;
            }
        }
        float bf[8];
        *(float4*)(bf)     = *(const float4*)(Bp + (size_t)k0 * ldb);
        *(float4*)(bf + 4) = *(const float4*)(Bp + (size_t)k0 * ldb + 4);

        __syncthreads();   // previous step's compute done reading smem

        // split + store A
        {
            uint32_t hi[8], lo[8];
            #pragma unroll
            for (int j = 0; j < 8; j++) {
                hi[j] = f2tf32(af[j]);
                lo[j] = f2tf32(af[j] - __uint_as_float(hi[j]));
            }
            *(uint4*)&Ah[arow][kq]     = *(uint4*)&hi[0];
            *(uint4*)&Ah[arow][kq + 4] = *(uint4*)&hi[4];
            *(uint4*)&Al[arow][kq]     = *(uint4*)&lo[0];
            *(uint4*)&Al[arow][kq + 4] = *(uint4*)&lo[4];
        }
        // split + store B
        {
            uint32_t hi[8], lo[8];
            #pragma unroll
            for (int j = 0; j < 8; j++) {
                hi[j] = f2tf32(bf[j]);
                lo[j] = f2tf32(bf[j] - __uint_as_float(hi[j]));
            }
            *(uint4*)&Bh[brow][bcol]     = *(uint4*)&hi[0];
            *(uint4*)&Bh[brow][bcol + 4] = *(uint4*)&hi[4];
            *(uint4*)&Bl[brow][bcol]     = *(uint4*)&lo[0];
            *(uint4*)&Bl[brow][bcol + 4] = *(uint4*)&lo[4];
        }
        __syncthreads();

        #pragma unroll
        for (int ks = 0; ks < 16; ks += 8) {
            uint32_t ahf[2][4], alf[2][4];
            #pragma unroll
            for (int mt = 0; mt < 2; mt++) {
                int r = wm * 32 + mt * 16 + lr;
                int c = ks + lc;
                ahf[mt][0] = Ah[r][c];     ahf[mt][1] = Ah[r + 8][c];
                ahf[mt][2] = Ah[r][c + 4]; ahf[mt][3] = Ah[r + 8][c + 4];
                alf[mt][0] = Al[r][c];     alf[mt][1] = Al[r + 8][c];
                alf[mt][2] = Al[r][c + 4]; alf[mt][3] = Al[r + 8][c + 4];
            }
            uint32_t bhf[8][2], blf[8][2];
            #pragma unroll
            for (int nt = 0; nt < 8; nt++) {
                int n = wn * 64 + nt * 8 + lr;
                bhf[nt][0] = Bh[ks + lc][n]; bhf[nt][1] = Bh[ks + 4 + lc][n];
                blf[nt][0] = Bl[ks + lc][n]; blf[nt][1] = Bl[ks + 4 + lc][n];
            }
            #pragma unroll
            for (int mt = 0; mt < 2; mt++)
                #pragma unroll
                for (int nt = 0; nt < 8; nt++) {
                    mma_tf32(acc[mt][nt], ahf[mt], bhf[nt]);
                    mma_tf32(acc[mt][nt], ahf[mt], blf[nt]);
                    mma_tf32(acc[mt][nt], alf[mt], bhf[nt]);
                }
        }
    }

    // epilogue
    #pragma unroll
    for (int mt = 0; mt < 2; mt++) {
        int r = m0 + wm * 32 + mt * 16 + lr;
        #pragma unroll
        for (int nt = 0; nt < 8; nt++) {
            int col = n0 + wn * 64 + nt * 8 + lc * 2;
            float2 v0 = make_float2(acc[mt][nt][0], acc[mt][nt][1]);
            float2 v1 = make_float2(acc[mt][nt][2], acc[mt][nt][3]);
            if (RELU_BIAS) {
                float b0v = __ldg(bias + col), b1v = __ldg(bias + col + 1);
                v0.x = fmaxf(v0.x + b0v, 0.f); v0.y = fmaxf(v0.y + b1v, 0.f);
                v1.x = fmaxf(v1.x + b0v, 0.f); v1.y = fmaxf(v1.y + b1v, 0.f);
            }
            if (r < M)     *(float2*)(C + (size_t)r * ldc + col) = v0;
            if (r + 8 < M) *(float2*)(C + (size_t)(r + 8) * ldc + col) = v1;
        }
    }
}

// narrow GEMM with fused layer-1 epilogue: U = relu(A/max(deg,1) + bias) @ W
__global__ void __launch_bounds__(256)
gemm_n16(const float* __restrict__ A, const float* __restrict__ W,
         const float* __restrict__ deg, const float* __restrict__ bias,
         float* __restrict__ U, int M)
{
    __shared__ float Ws[128 * OUTD];
    __shared__ float As[64][132];
    int tid = threadIdx.x;
    int r0  = blockIdx.x * 64;

    for (int i = tid; i < 128 * OUTD; i += 256) Ws[i] = W[i];
    for (int f = tid; f < 2048; f += 256) {
        int row = f >> 5, k4 = (f & 31) << 2;
        int gr = r0 + row;
        float4 v = make_float4(0.f, 0.f, 0.f, 0.f);
        if (gr < M) {
            float inv = 1.f / fmaxf(__ldg(deg + gr), 1.f);
            v = *(const float4*)(A + (size_t)gr * H + k4);
            v.x = fmaxf(v.x * inv + __ldg(bias + k4 + 0), 0.f);
            v.y = fmaxf(v.y * inv + __ldg(bias + k4 + 1), 0.f);
            v.z = fmaxf(v.z * inv + __ldg(bias + k4 + 2), 0.f);
            v.w = fmaxf(v.w * inv + __ldg(bias + k4 + 3), 0.f);
        }
        *(float4*)&As[row][k4] = v;
    }
    __syncthreads();

    int col = tid & 15;
    int rb  = (tid >> 4) * 4;
    float a0 = 0.f, a1 = 0.f, a2 = 0.f, a3 = 0.f;
    #pragma unroll 8
    for (int k = 0; k < 128; k++) {
        float w = Ws[k * OUTD + col];
        a0 += As[rb + 0][k] * w;
        a1 += As[rb + 1][k] * w;
        a2 += As[rb + 2][k] * w;
        a3 += As[rb + 3][k] * w;
    }
    if (r0 + rb + 0 < M) U[(size_t)(r0 + rb + 0) * OUTD + col] = a0;
    if (r0 + rb + 1 < M) U[(size_t)(r0 + rb + 1) * OUTD + col] = a1;
    if (r0 + rb + 2 < M) U[(size_t)(r0 + rb + 2) * OUTD + col] = a2;
    if (r0 + rb + 3 < M) U[(size_t)(r0 + rb + 3) * OUTD + col] = a3;
}

__global__ void final_combine(const float* __restrict__ aggd,
                              const float* __restrict__ deg0, const float* __restrict__ deg1,
                              const float* __restrict__ bias2, float* __restrict__ out)
{
    int i = blockIdx.x * blockDim.x + threadIdx.x;
    if (i >= ND * OUTD) return;
    int m = i >> 4, c = i & 15;
    float i0 = 1.f / fmaxf(__ldg(deg0 + m), 1.f);
    float i1 = 1.f / fmaxf(__ldg(deg1 + m), 1.f);
    out[i] = aggd[i] * i0 + aggd[ND * OUTD + i] * i1 + __ldg(bias2 + c);
}

// ---------------- launch ----------------
extern "C" void kernel_launch(void* const* d_in, const int* in_sizes, int n_in,
                              void* d_out, int out_size)
{
    const float* feat_a = (const float*)d_in[0];
    const float* feat_b = (const float*)d_in[1];
    const float* basis0 = (const float*)d_in[3];
    const float* coef0  = (const float*)d_in[4];
    const float* bias0  = (const float*)d_in[5];
    const float* basis1 = (const float*)d_in[6];
    const float* coef1  = (const float*)d_in[7];
    const float* bias1  = (const float*)d_in[8];
    const float* basis2 = (const float*)d_in[9];
    const float* coef2  = (const float*)d_in[10];
    const float* bias2  = (const float*)d_in[11];
    const int* e0s = (const int*)d_in[12]; const int* e0d = (const int*)d_in[13];
    const int* e1s = (const int*)d_in[14]; const int* e1d = (const int*)d_in[15];
    const int* e2s = (const int*)d_in[16]; const int* e2d = (const int*)d_in[17];
    const int* e3s = (const int*)d_in[18]; const int* e3d = (const int*)d_in[19];
    float* out = (float*)d_out;

    void *p;
    float *agg0, *h0d, *t, *h1a, *h1b, *u0, *u1, *aggd, *dg0, *dg1, *dg2, *dg3, *w0, *w1, *w2;
    cudaGetSymbolAddress(&p, g_agg0); agg0 = (float*)p; t = agg0;  // aliased reuse
    cudaGetSymbolAddress(&p, g_h0d);  h0d  = (float*)p;
    cudaGetSymbolAddress(&p, g_h1a);  h1a  = (float*)p;
    cudaGetSymbolAddress(&p, g_h1b);  h1b  = (float*)p;
    cudaGetSymbolAddress(&p, g_u0);   u0   = (float*)p;
    cudaGetSymbolAddress(&p, g_u1);   u1   = (float*)p;
    cudaGetSymbolAddress(&p, g_aggd); aggd = (float*)p;
    cudaGetSymbolAddress(&p, g_deg0); dg0  = (float*)p;
    cudaGetSymbolAddress(&p, g_deg1); dg1  = (float*)p;
    cudaGetSymbolAddress(&p, g_deg2); dg2  = (float*)p;
    cudaGetSymbolAddress(&p, g_deg3); dg3  = (float*)p;
    cudaGetSymbolAddress(&p, g_w0);   w0   = (float*)p;
    cudaGetSymbolAddress(&p, g_w1);   w1   = (float*)p;
    cudaGetSymbolAddress(&p, g_w2);   w2   = (float*)p;

    cudaMemsetAsync(agg0, 0, sizeof(float) * (size_t)ND * 256);
    cudaMemsetAsync(h1a,  0, sizeof(float) * (size_t)NA * H);
    cudaMemsetAsync(h1b,  0, sizeof(float) * (size_t)NB * H);
    cudaMemsetAsync(aggd, 0, sizeof(float) * (size_t)ND * 2 * OUTD);
    cudaMemsetAsync(dg0,  0, sizeof(float) * ND);
    cudaMemsetAsync(dg1,  0, sizeof(float) * ND);
    cudaMemsetAsync(dg2,  0, sizeof(float) * NA);
    cudaMemsetAsync(dg3,  0, sizeof(float) * NB);

    // 5 make_w launches first, so the 6th kernel launch (ncu -s 5 -c 1 capture
    // target) is the first heavy scatter128.
    make_w<<<32, 256>>>(basis0, coef0, 0, H, H, H,   w0);                // 1
    make_w<<<32, 256>>>(basis0, coef0, 1, H, H, H,   w0 + H * H);        // 2
    make_w<<<32, 256>>>(basis1, coef1, 2, H, H, 256, w1);                // 3
    make_w<<<32, 256>>>(basis1, coef1, 3, H, H, 256, w1 + 128);          // 4
    make_w<<<32, 256>>>(basis2, coef2, 0, H, OUTD, OUTD, w2);            // 5
    scatter128<true><<<4096, 256>>>(feat_a, H, 0, e0s, e0d, agg0, 256, 0, dg0); // 6 <- profiled
    make_w<<<32, 256>>>(basis2, coef2, 1, H, OUTD, OUTD, w2 + H * OUTD); // 7
    scatter128<true><<<4096, 256>>>(feat_b, H, 0, e1s, e1d, agg0, 256, 128, dg1);

    // ---- layer 0: fused K=256 tensor GEMM + deg-scale + bias + relu
    dim3 g0((ND + 127) / 128, 1);
    tgemm<true, true><<<g0, 256>>>(agg0, 256, w0, 128, h0d, 128, ND, 256, dg0, dg1, bias0);

    // ---- layer 1: transform first (50k rows), then scatter 128-dim to a and b
    dim3 g1((ND + 127) / 128, 2);
    tgemm<false, false><<<g1, 256>>>(h0d, 128, w1, 256, t, 256, ND, 128, nullptr, nullptr, nullptr);
    scatter128<true><<<4096, 256>>>(t, 256, 0,   e2s, e2d, h1a, H, 0, dg2);
    scatter128<true><<<4096, 256>>>(t, 256, 128, e3s, e3d, h1b, H, 0, dg3);

    // ---- layer 2: fused (deg-norm + bias + relu) into narrow GEMM, then 16-dim scatter
    gemm_n16<<<(NA + 63) / 64, 256>>>(h1a, w2,            dg2, bias1, u0, NA);
    gemm_n16<<<(NB + 63) / 64, 256>>>(h1b, w2 + H * OUTD, dg3, bias1, u1, NB);
    scatter16<<<2048, 256>>>(u0, e0s, e0d, aggd);
    scatter16<<<2048, 256>>>(u1, e1s, e1d, aggd + ND * OUTD);
    final_combine<<<(ND * OUTD + 255) / 256, 256>>>(aggd, dg0, dg1, bias2, out);
}